// round 1
// baseline (speedup 1.0000x reference)
#include <cuda_runtime.h>
#include <stdint.h>

#define Bv 16
#define Cv 64
#define Hv 64
#define Wv 64
#define Kv 1024
#define Dv 64
#define HW (Hv*Wv)                 // 4096
#define NPIX (Bv*Hv*Wv)            // 65536
#define NUMEL (Bv*Cv*Hv*Wv)        // 4194304
#define CHUNK 128
#define NCHUNK (Kv/CHUNK)

__device__ float g_c2[Kv];
__device__ float g_loss;

// Packed fp32x2 FMA (sm_103a): acc = a*b + acc, two lanes at once.
#define FMA2(acc, a, b) \
    asm("fma.rn.f32x2 %0, %1, %2, %0;" : "+l"(acc) : "l"(a), "l"(b))
#define ADD2(out, a, b) \
    asm("add.rn.f32x2 %0, %1, %2;" : "=l"(out) : "l"(a), "l"(b))

// --- Kernel 0: zero loss accumulator, precompute ||e_k||^2 -------------------
__global__ void vq_prep(const float* __restrict__ emb) {
    int k = blockIdx.x * blockDim.x + threadIdx.x;
    if (k == 0) g_loss = 0.0f;
    if (k < Kv) {
        const float* e = emb + k * Dv;
        float s0 = 0.f, s1 = 0.f, s2 = 0.f, s3 = 0.f;
        #pragma unroll
        for (int i = 0; i < Dv; i += 4) {
            s0 += e[i + 0] * e[i + 0];
            s1 += e[i + 1] * e[i + 1];
            s2 += e[i + 2] * e[i + 2];
            s3 += e[i + 3] * e[i + 3];
        }
        g_c2[k] = __fadd_rn(__fadd_rn(s0, s1), __fadd_rn(s2, s3));
    }
}

// --- Kernel 1: main argmin + quantize + loss partials ------------------------
// 128 threads/block, 1 pixel per thread, 512 blocks.
__global__ __launch_bounds__(128) void vq_main(const float* __restrict__ in,
                                               const float* __restrict__ emb,
                                               float* __restrict__ out) {
    __shared__ float4 se[CHUNK * 16];   // 128 codes x 64 floats = 32 KB
    __shared__ float  sc2[CHUNK];

    const int p = blockIdx.x * 128 + threadIdx.x;
    const int b = p >> 12;
    const int h = (p >> 6) & 63;
    const int w = p & 63;
    const float* xin = in + ((b * Cv) * Hv + h) * Wv + w;  // + c*HW per channel

    // Load this pixel's 64-d vector into registers as 32 packed f32x2 pairs.
    unsigned long long xp[32];
    float s0 = 0.f, s1 = 0.f, s2 = 0.f, s3 = 0.f;
    #pragma unroll
    for (int i = 0; i < 32; i++) {
        float f0 = xin[(2 * i + 0) * HW];
        float f1 = xin[(2 * i + 1) * HW];
        xp[i] = ((unsigned long long)__float_as_uint(f1) << 32) | __float_as_uint(f0);
        if (i & 1) { s1 += f0 * f0; s3 += f1 * f1; }
        else       { s0 += f0 * f0; s2 += f1 * f1; }
    }
    const float sx = __fadd_rn(__fadd_rn(s0, s1), __fadd_rn(s2, s3));

    float best = 3.4e38f;
    int bestk = 0;

    for (int ch = 0; ch < NCHUNK; ch++) {
        __syncthreads();
        const float4* g = (const float4*)(emb + ch * CHUNK * Dv);
        #pragma unroll
        for (int i = 0; i < 16; i++)
            se[threadIdx.x + i * 128] = g[threadIdx.x + i * 128];
        sc2[threadIdx.x] = g_c2[ch * CHUNK + threadIdx.x];
        __syncthreads();

        #pragma unroll 2
        for (int kk = 0; kk < CHUNK; kk++) {
            const ulonglong2* ep = (const ulonglong2*)&se[kk * 16];
            unsigned long long a0 = 0ull, a1 = 0ull, a2 = 0ull, a3 = 0ull;
            #pragma unroll
            for (int i = 0; i < 8; i++) {
                ulonglong2 e0 = ep[2 * i + 0];   // broadcast LDS.128
                ulonglong2 e1 = ep[2 * i + 1];
                FMA2(a0, xp[4 * i + 0], e0.x);
                FMA2(a1, xp[4 * i + 1], e0.y);
                FMA2(a2, xp[4 * i + 2], e1.x);
                FMA2(a3, xp[4 * i + 3], e1.y);
            }
            unsigned long long t0, t1;
            ADD2(t0, a0, a1);
            ADD2(t1, a2, a3);
            ADD2(t0, t0, t1);
            float dot = __fadd_rn(__uint_as_float((unsigned)t0),
                                  __uint_as_float((unsigned)(t0 >> 32)));
            // mirror reference: (||x||^2 + ||e||^2) - 2*(x.e), round-to-nearest, no contraction
            float dist = __fsub_rn(__fadd_rn(sx, sc2[kk]), __fmul_rn(2.0f, dot));
            if (dist < best) { best = dist; bestk = ch * CHUNK + kk; }  // first-index tie-break
        }
    }

    // Epilogue: write quantized vector (BCHW layout) + local loss partial.
    const float4* eb = (const float4*)(emb + bestk * Dv);
    float* op = out + ((b * Cv) * Hv + h) * Wv + w;
    float ls = 0.f;
    #pragma unroll
    for (int i = 0; i < 16; i++) {
        float4 q = eb[i];
        float f0 = __uint_as_float((unsigned)(xp[2 * i + 0]));
        float f1 = __uint_as_float((unsigned)(xp[2 * i + 0] >> 32));
        float f2 = __uint_as_float((unsigned)(xp[2 * i + 1]));
        float f3 = __uint_as_float((unsigned)(xp[2 * i + 1] >> 32));
        op[(4 * i + 0) * HW] = q.x;
        op[(4 * i + 1) * HW] = q.y;
        op[(4 * i + 2) * HW] = q.z;
        op[(4 * i + 3) * HW] = q.w;
        float d0 = q.x - f0, d1 = q.y - f1, d2 = q.z - f2, d3 = q.w - f3;
        ls += d0 * d0 + d1 * d1 + d2 * d2 + d3 * d3;
    }
    #pragma unroll
    for (int off = 16; off; off >>= 1)
        ls += __shfl_xor_sync(0xffffffffu, ls, off);
    if ((threadIdx.x & 31) == 0)
        atomicAdd(&g_loss, ls);
}

// --- Kernel 2: finalize loss -------------------------------------------------
__global__ void vq_loss(float* __restrict__ out, int out_size) {
    if (out_size > NUMEL)
        out[NUMEL] = 1.25f * g_loss / (float)NUMEL;
}

extern "C" void kernel_launch(void* const* d_in, const int* in_sizes, int n_in,
                              void* d_out, int out_size) {
    const float* in  = (const float*)d_in[0];
    const float* emb = (const float*)d_in[1];
    float* out = (float*)d_out;

    vq_prep<<<(Kv + 255) / 256, 256>>>(emb);
    vq_main<<<NPIX / 128, 128>>>(in, emb, out);
    vq_loss<<<1, 1>>>(out, out_size);
}

// round 4
// speedup vs baseline: 3.9794x; 3.9794x over previous
#include <cuda_runtime.h>
#include <cuda_bf16.h>
#include <stdint.h>

// Problem constants
#define HWv 4096
#define NPIXv 65536
#define NUMELv 4194304
#define NT 128              // codes per tile
#define NTILES 8            // 8*128 = 1024 codes
#define BLKPIX 256          // pixels per block
#define GRIDv (NPIXv/BLKPIX)  // 256 blocks

// SMEM byte offsets (dynamic). All MMA tiles have 128B rows, SW128-swizzled.
#define SM_AHI  0
#define SM_ALO  32768
#define SM_B    65536
#define SM_BOFF(buf,half) (SM_B + ((buf)*2 + (half))*16384)
#define SM_SC2  (SM_B + 4*16384)          // 2 buffers * 128 floats
#define SM_X    (SM_SC2 + 1024)           // 256 rows * 65 floats (padded)
#define SM_TOTAL (SM_X + BLKPIX*65*4)

__device__ float    g_loss;
__device__ unsigned g_count;

static __device__ __forceinline__ uint32_t s2u(const void* p) {
    uint32_t a;
    asm("{ .reg .u64 t; cvta.to.shared.u64 t, %1; cvt.u32.u64 %0, t; }" : "=r"(a) : "l"(p));
    return a;
}
// SW128 swizzle on byte offsets within a 128B-row tile (conflict-free ldmatrix)
static __device__ __forceinline__ uint32_t swz(uint32_t base, int row, int kb) {
    uint32_t o = (uint32_t)(row * 128 + kb);
    return base + (o ^ ((o >> 3) & 0x70));
}

#define LDSM4(R, addr) \
    asm volatile("ldmatrix.sync.aligned.m8n8.x4.shared.b16 {%0,%1,%2,%3}, [%4];" \
        : "=r"((R)[0]), "=r"((R)[1]), "=r"((R)[2]), "=r"((R)[3]) : "r"(addr))
#define LDSM2(R, addr) \
    asm volatile("ldmatrix.sync.aligned.m8n8.x2.shared.b16 {%0,%1}, [%2];" \
        : "=r"((R)[0]), "=r"((R)[1]) : "r"(addr))
#define MMA(D, A, B) \
    asm volatile("mma.sync.aligned.m16n8k16.row.col.f32.bf16.bf16.f32 " \
        "{%0,%1,%2,%3}, {%4,%5,%6,%7}, {%8,%9}, {%0,%1,%2,%3};" \
        : "+f"((D)[0]), "+f"((D)[1]), "+f"((D)[2]), "+f"((D)[3]) \
        : "r"((A)[0]), "r"((A)[1]), "r"((A)[2]), "r"((A)[3]), "r"((B)[0]), "r"((B)[1]))

// Load one B tile (128 codes x 64 ch) as bf16 hi/lo into smem + c2 partials.
// Only threads 0..127 participate (one code row each).
static __device__ __forceinline__ void load_btile(char* sm, const float* __restrict__ emb,
                                                  int t, int buf, int tid) {
    const int k = t * NT + tid;
    const float4* er = (const float4*)(emb + k * 64);
    char* bhp = sm + SM_BOFF(buf, 0);
    char* blp = sm + SM_BOFF(buf, 1);
    float s0 = 0.f, s1 = 0.f, s2 = 0.f, s3 = 0.f;
    #pragma unroll
    for (int i = 0; i < 16; i++) {
        float4 v = er[i];
        s0 = __fmaf_rn(v.x, v.x, s0);
        s1 = __fmaf_rn(v.y, v.y, s1);
        s2 = __fmaf_rn(v.z, v.z, s2);
        s3 = __fmaf_rn(v.w, v.w, s3);
        __nv_bfloat16 h0 = __float2bfloat16(v.x), h1 = __float2bfloat16(v.y);
        __nv_bfloat16 h2 = __float2bfloat16(v.z), h3 = __float2bfloat16(v.w);
        __nv_bfloat16 l0 = __float2bfloat16(__fsub_rn(v.x, __bfloat162float(h0)));
        __nv_bfloat16 l1 = __float2bfloat16(__fsub_rn(v.y, __bfloat162float(h1)));
        __nv_bfloat16 l2 = __float2bfloat16(__fsub_rn(v.z, __bfloat162float(h2)));
        __nv_bfloat16 l3 = __float2bfloat16(__fsub_rn(v.w, __bfloat162float(h3)));
        uint32_t ph0 = ((uint32_t)__bfloat16_as_ushort(h1) << 16) | __bfloat16_as_ushort(h0);
        uint32_t ph1 = ((uint32_t)__bfloat16_as_ushort(h3) << 16) | __bfloat16_as_ushort(h2);
        uint32_t pl0 = ((uint32_t)__bfloat16_as_ushort(l1) << 16) | __bfloat16_as_ushort(l0);
        uint32_t pl1 = ((uint32_t)__bfloat16_as_ushort(l3) << 16) | __bfloat16_as_ushort(l2);
        uint32_t o0 = (uint32_t)(tid * 128 + (4*i) * 2);
        uint32_t o1 = (uint32_t)(tid * 128 + (4*i + 2) * 2);
        o0 = o0 ^ ((o0 >> 3) & 0x70);
        o1 = o1 ^ ((o1 >> 3) & 0x70);
        *(uint32_t*)(bhp + o0) = ph0;  *(uint32_t*)(bhp + o1) = ph1;
        *(uint32_t*)(blp + o0) = pl0;  *(uint32_t*)(blp + o1) = pl1;
    }
    ((float*)(sm + SM_SC2))[buf * 128 + tid] =
        __fadd_rn(__fadd_rn(s0, s1), __fadd_rn(s2, s3));
}

// Exact fp32 distance, replicating Round-1's (verified 0-flip) summation structure.
static __device__ __forceinline__ float exact_dist(const float* x, const float* __restrict__ e,
                                                   float sx) {
    const float4* e4 = (const float4*)e;
    float cc0=0,cc1=0,cc2=0,cc3=0,cc4=0,cc5=0,cc6=0,cc7=0;
    float s0=0,s1=0,s2=0,s3=0;
    #pragma unroll
    for (int i = 0; i < 16; i++) {
        float4 v = e4[i];
        s0 = __fmaf_rn(v.x, v.x, s0);
        s1 = __fmaf_rn(v.y, v.y, s1);
        s2 = __fmaf_rn(v.z, v.z, s2);
        s3 = __fmaf_rn(v.w, v.w, s3);
        float x0 = x[4*i], x1 = x[4*i+1], x2 = x[4*i+2], x3 = x[4*i+3];
        if ((i & 1) == 0) {
            cc0 = __fmaf_rn(x0, v.x, cc0); cc1 = __fmaf_rn(x1, v.y, cc1);
            cc2 = __fmaf_rn(x2, v.z, cc2); cc3 = __fmaf_rn(x3, v.w, cc3);
        } else {
            cc4 = __fmaf_rn(x0, v.x, cc4); cc5 = __fmaf_rn(x1, v.y, cc5);
            cc6 = __fmaf_rn(x2, v.z, cc6); cc7 = __fmaf_rn(x3, v.w, cc7);
        }
    }
    float c2 = __fadd_rn(__fadd_rn(s0, s1), __fadd_rn(s2, s3));
    float lo = __fadd_rn(__fadd_rn(cc0, cc2), __fadd_rn(cc4, cc6));
    float hi = __fadd_rn(__fadd_rn(cc1, cc3), __fadd_rn(cc5, cc7));
    float dot = __fadd_rn(lo, hi);
    return __fsub_rn(__fadd_rn(sx, c2), __fmul_rn(2.0f, dot));
}

static __device__ __forceinline__ void upd2(unsigned& b1, unsigned& b2, unsigned km) {
    unsigned mx = (b1 > km) ? b1 : km;
    b1 = (b1 < km) ? b1 : km;
    b2 = (b2 < mx) ? b2 : mx;
}

__global__ __launch_bounds__(BLKPIX, 1) void vq_main(const float* __restrict__ in,
                                                     const float* __restrict__ emb,
                                                     float* __restrict__ out,
                                                     int out_size) {
    extern __shared__ char sm[];
    const uint32_t sb = s2u(sm);
    const int tid  = threadIdx.x;
    const int lane = tid & 31;
    const int q    = lane >> 2;        // 0..7
    const int qp   = lane & 3;         // 0..3
    const int wrow = (tid >> 5) * 32;  // warp's 32-pixel stripe

    // ---- prologue: load x (BCHW, channel-strided), stash fp32, split bf16 hi/lo ----
    const int p0 = blockIdx.x * BLKPIX + tid;
    const int b0 = p0 >> 12, h0i = (p0 >> 6) & 63, w0 = p0 & 63;
    const float* xin = in + ((b0 * 64) * 64 + h0i) * 64 + w0;
    float* xs = (float*)(sm + SM_X) + tid * 65;
    #pragma unroll
    for (int c = 0; c < 64; c += 2) {
        float f0 = xin[c * HWv], f1 = xin[(c + 1) * HWv];
        xs[c] = f0; xs[c + 1] = f1;
        __nv_bfloat16 hh0 = __float2bfloat16(f0), hh1 = __float2bfloat16(f1);
        __nv_bfloat16 ll0 = __float2bfloat16(__fsub_rn(f0, __bfloat162float(hh0)));
        __nv_bfloat16 ll1 = __float2bfloat16(__fsub_rn(f1, __bfloat162float(hh1)));
        uint32_t ph = ((uint32_t)__bfloat16_as_ushort(hh1) << 16) | __bfloat16_as_ushort(hh0);
        uint32_t pl = ((uint32_t)__bfloat16_as_ushort(ll1) << 16) | __bfloat16_as_ushort(ll0);
        uint32_t off = (uint32_t)(tid * 128 + c * 2);
        off = off ^ ((off >> 3) & 0x70);
        *(uint32_t*)(sm + SM_AHI + off) = ph;
        *(uint32_t*)(sm + SM_ALO + off) = pl;
    }
    if (tid < NT) load_btile(sm, emb, 0, 0, tid);
    __syncthreads();

    // running top-2 packed keys, one pair per row-slot s (row = q + s*8)
    unsigned t1[4] = {0xFFFFFFFFu, 0xFFFFFFFFu, 0xFFFFFFFFu, 0xFFFFFFFFu};
    unsigned t2[4] = {0xFFFFFFFFu, 0xFFFFFFFFu, 0xFFFFFFFFu, 0xFFFFFFFFu};

    for (int t = 0; t < NTILES; t++) {
        const int buf = t & 1;
        if (t < NTILES - 1 && tid < NT) load_btile(sm, emb, t + 1, buf ^ 1, tid);

        const uint32_t bhB = sb + SM_BOFF(buf, 0);
        const uint32_t blB = sb + SM_BOFF(buf, 1);

        float acc[32][4];
        #pragma unroll
        for (int i = 0; i < 32; i++) {
            acc[i][0] = 0.f; acc[i][1] = 0.f; acc[i][2] = 0.f; acc[i][3] = 0.f;
        }

        #pragma unroll
        for (int ks = 0; ks < 4; ks++) {
            const int akb = ks * 32 + (lane >> 4) * 16;
            uint32_t Ah0[4], Ah1[4], Al0[4], Al1[4];
            LDSM4(Ah0, swz(sb + SM_AHI, wrow + (lane & 15), akb));
            LDSM4(Ah1, swz(sb + SM_AHI, wrow + 16 + (lane & 15), akb));
            LDSM4(Al0, swz(sb + SM_ALO, wrow + (lane & 15), akb));
            LDSM4(Al1, swz(sb + SM_ALO, wrow + 16 + (lane & 15), akb));
            const int bkb = ks * 32 + ((lane >> 3) & 1) * 16;
            #pragma unroll
            for (int cf = 0; cf < 16; cf += 2) {
                uint32_t Bh0[2], Bl0[2], Bh1[2], Bl1[2];
                LDSM2(Bh0, swz(bhB, cf * 8 + (lane & 7), bkb));
                LDSM2(Bl0, swz(blB, cf * 8 + (lane & 7), bkb));
                LDSM2(Bh1, swz(bhB, (cf + 1) * 8 + (lane & 7), bkb));
                LDSM2(Bl1, swz(blB, (cf + 1) * 8 + (lane & 7), bkb));
                MMA(acc[cf*2+0], Ah0, Bh0); MMA(acc[cf*2+1], Ah1, Bh0);
                MMA(acc[cf*2+2], Ah0, Bh1); MMA(acc[cf*2+3], Ah1, Bh1);
                MMA(acc[cf*2+0], Ah0, Bl0); MMA(acc[cf*2+1], Ah1, Bl0);
                MMA(acc[cf*2+2], Ah0, Bl1); MMA(acc[cf*2+3], Ah1, Bl1);
                MMA(acc[cf*2+0], Al0, Bh0); MMA(acc[cf*2+1], Al1, Bh0);
                MMA(acc[cf*2+2], Al0, Bh1); MMA(acc[cf*2+3], Al1, Bh1);
            }
        }

        // reduce: dist = c2 - 2*dot (sx dropped: per-row constant), top-2 packed keys
        const float* sc2p = (const float*)(sm + SM_SC2) + buf * 128;
        #pragma unroll
        for (int cf = 0; cf < 16; cf++) {
            float2 c2v = *(const float2*)(sc2p + cf * 8 + qp * 2);
            const unsigned code = (unsigned)(t * NT + cf * 8 + qp * 2);
            #pragma unroll
            for (int rf = 0; rf < 2; rf++) {
                #pragma unroll
                for (int i = 0; i < 4; i++) {
                    float dist = __fmaf_rn(-2.0f, acc[cf*2+rf][i], (i & 1) ? c2v.y : c2v.x);
                    unsigned u   = (unsigned)__float_as_int(dist);
                    unsigned key = u ^ ((unsigned)(((int)u) >> 31) | 0x80000000u);
                    unsigned km  = (key & 0xFFFFFC00u) | (code + (unsigned)(i & 1));
                    const int s = rf * 2 + (i >> 1);
                    upd2(t1[s], t2[s], km);
                }
            }
        }
        __syncthreads();
    }

    // merge top-2 across the quad (each thread held a 32-code column subset)
    #pragma unroll
    for (int s = 0; s < 4; s++) {
        #pragma unroll
        for (int m = 1; m <= 2; m <<= 1) {
            unsigned r1 = __shfl_xor_sync(0xffffffffu, t1[s], m);
            unsigned r2 = __shfl_xor_sync(0xffffffffu, t2[s], m);
            unsigned mx = (t1[s] > r1) ? t1[s] : r1;
            t1[s] = (t1[s] < r1) ? t1[s] : r1;
            unsigned mn2 = (t2[s] < r2) ? t2[s] : r2;
            t2[s] = (mn2 < mx) ? mn2 : mx;
        }
    }
    // thread takes row-slot s = qp  -> pixel row wrow + q + qp*8
    unsigned f1 = t1[0], f2 = t2[0];
    if (qp == 1) { f1 = t1[1]; f2 = t2[1]; }
    if (qp == 2) { f1 = t1[2]; f2 = t2[2]; }
    if (qp == 3) { f1 = t1[3]; f2 = t2[3]; }

    const int p_local = wrow + q + qp * 8;
    const int p = blockIdx.x * BLKPIX + p_local;
    const int b = p >> 12, h = (p >> 6) & 63, w = p & 63;

    // ---- exact fp32 rescore of both candidates ----
    const float* xsr = (const float*)(sm + SM_X) + p_local * 65;
    float x_[64];
    #pragma unroll
    for (int c = 0; c < 64; c++) x_[c] = xsr[c];
    float s0 = 0.f, s1 = 0.f, s2 = 0.f, s3 = 0.f;
    #pragma unroll
    for (int i = 0; i < 32; i++) {
        float f0v = x_[2*i], f1v = x_[2*i + 1];
        if (i & 1) { s1 = __fmaf_rn(f0v, f0v, s1); s3 = __fmaf_rn(f1v, f1v, s3); }
        else       { s0 = __fmaf_rn(f0v, f0v, s0); s2 = __fmaf_rn(f1v, f1v, s2); }
    }
    const float sx = __fadd_rn(__fadd_rn(s0, s1), __fadd_rn(s2, s3));
    const int k1 = (int)(f1 & 1023u), k2 = (int)(f2 & 1023u);
    const float d1 = exact_dist(x_, emb + k1 * 64, sx);
    const float d2 = exact_dist(x_, emb + k2 * 64, sx);
    const int kwin = ((d2 < d1) || (d2 == d1 && k2 < k1)) ? k2 : k1;

    // ---- write quantized output (BCHW) + loss partial ----
    const float4* eb = (const float4*)(emb + kwin * 64);
    float* op = out + ((b * 64) * 64 + h) * 64 + w;
    float ls = 0.f;
    #pragma unroll
    for (int i = 0; i < 16; i++) {
        float4 qv = eb[i];
        op[(4*i + 0) * HWv] = qv.x;
        op[(4*i + 1) * HWv] = qv.y;
        op[(4*i + 2) * HWv] = qv.z;
        op[(4*i + 3) * HWv] = qv.w;
        float e0 = qv.x - x_[4*i],   e1 = qv.y - x_[4*i+1];
        float e2 = qv.z - x_[4*i+2], e3 = qv.w - x_[4*i+3];
        ls += e0*e0 + e1*e1 + e2*e2 + e3*e3;
    }
    #pragma unroll
    for (int off = 16; off; off >>= 1)
        ls += __shfl_xor_sync(0xffffffffu, ls, off);
    if (lane == 0) atomicAdd(&g_loss, ls);

    // ---- last-block ticket: finalize loss, reset for next graph replay ----
    __syncthreads();
    if (tid == 0) {
        __threadfence();
        unsigned v = atomicAdd(&g_count, 1u);
        if (v == GRIDv - 1) {
            __threadfence();
            if (out_size > NUMELv)
                out[NUMELv] = 1.25f * g_loss / (float)NUMELv;
            g_loss = 0.f;
            g_count = 0u;
        }
    }
}

extern "C" void kernel_launch(void* const* d_in, const int* in_sizes, int n_in,
                              void* d_out, int out_size) {
    const float* in  = (const float*)d_in[0];
    const float* emb = (const float*)d_in[1];
    float* out = (float*)d_out;

    cudaFuncSetAttribute(vq_main, cudaFuncAttributeMaxDynamicSharedMemorySize, SM_TOTAL);
    vq_main<<<GRIDv, BLKPIX, SM_TOTAL>>>(in, emb, out, out_size);
}

// round 5
// speedup vs baseline: 4.7335x; 1.1895x over previous
#include <cuda_runtime.h>
#include <cuda_bf16.h>
#include <stdint.h>

// Problem constants
#define HWv 4096
#define NPIXv 65536
#define NUMELv 4194304
#define NT 128               // codes per tile
#define NTILES 8
#define BLKPIX 256           // pixels per block
#define GRIDv (NPIXv/BLKPIX) // 256 blocks -> exactly 1 wave at 2 CTAs/SM

// Dynamic SMEM layout (bytes)
#define SM_AHI 0            // 256 rows x 128B (x hi, SW128)
#define SM_ALO 32768        // 256 rows x 128B (x lo)
#define SM_BH  65536        // 128 rows x 128B (codes hi)
#define SM_BL  81920        // 128 rows x 128B (codes lo)
#define SM_C2  98304        // 1024 floats
#define SM_TOTAL (98304 + 4096)

// Prepacked codebook: exact byte image of the swizzled smem B tiles.
__device__ __align__(16) unsigned char g_bh[NTILES][16384];
__device__ __align__(16) unsigned char g_bl[NTILES][16384];
__device__ float    g_c2[1024];
__device__ float    g_loss;
__device__ unsigned g_count;

static __device__ __forceinline__ uint32_t s2u(const void* p) {
    uint32_t a;
    asm("{ .reg .u64 t; cvta.to.shared.u64 t, %1; cvt.u32.u64 %0, t; }" : "=r"(a) : "l"(p));
    return a;
}
static __device__ __forceinline__ uint32_t swz(uint32_t base, int row, int kb) {
    uint32_t o = (uint32_t)(row * 128 + kb);
    return base + (o ^ ((o >> 3) & 0x70));
}
static __device__ __forceinline__ unsigned umaxu(unsigned a, unsigned b) { return a > b ? a : b; }
static __device__ __forceinline__ unsigned uminu(unsigned a, unsigned b) { return a < b ? a : b; }

#define LDSM4(R, addr) \
    asm volatile("ldmatrix.sync.aligned.m8n8.x4.shared.b16 {%0,%1,%2,%3}, [%4];" \
        : "=r"((R)[0]), "=r"((R)[1]), "=r"((R)[2]), "=r"((R)[3]) : "r"(addr))
#define MMA(D, A, B) \
    asm volatile("mma.sync.aligned.m16n8k16.row.col.f32.bf16.bf16.f32 " \
        "{%0,%1,%2,%3}, {%4,%5,%6,%7}, {%8,%9}, {%0,%1,%2,%3};" \
        : "+f"((D)[0]), "+f"((D)[1]), "+f"((D)[2]), "+f"((D)[3]) \
        : "r"((A)[0]), "r"((A)[1]), "r"((A)[2]), "r"((A)[3]), "r"((B)[0]), "r"((B)[1]))

static __device__ __forceinline__ void cp16(uint32_t dst, const void* src) {
    uint64_t g;
    asm("cvta.to.global.u64 %0, %1;" : "=l"(g) : "l"(src));
    asm volatile("cp.async.cg.shared.global [%0], [%1], 16;" :: "r"(dst), "l"(g));
}

// --- Kernel 0: prepack codebook (bf16 hi/lo, SW128 tile image) + c2 ---------
__global__ __launch_bounds__(NT) void vq_prep(const float* __restrict__ emb) {
    const int t = blockIdx.x, row = threadIdx.x;
    const int k = t * NT + row;
    const float4* er = (const float4*)(emb + k * 64);
    unsigned char* bh = g_bh[t];
    unsigned char* bl = g_bl[t];
    float s0 = 0.f, s1 = 0.f, s2 = 0.f, s3 = 0.f;
    #pragma unroll
    for (int i = 0; i < 16; i++) {
        float4 v = er[i];
        s0 = __fmaf_rn(v.x, v.x, s0);
        s1 = __fmaf_rn(v.y, v.y, s1);
        s2 = __fmaf_rn(v.z, v.z, s2);
        s3 = __fmaf_rn(v.w, v.w, s3);
        __nv_bfloat16 h0 = __float2bfloat16(v.x), h1 = __float2bfloat16(v.y);
        __nv_bfloat16 h2 = __float2bfloat16(v.z), h3 = __float2bfloat16(v.w);
        __nv_bfloat16 l0 = __float2bfloat16(__fsub_rn(v.x, __bfloat162float(h0)));
        __nv_bfloat16 l1 = __float2bfloat16(__fsub_rn(v.y, __bfloat162float(h1)));
        __nv_bfloat16 l2 = __float2bfloat16(__fsub_rn(v.z, __bfloat162float(h2)));
        __nv_bfloat16 l3 = __float2bfloat16(__fsub_rn(v.w, __bfloat162float(h3)));
        uint32_t ph0 = ((uint32_t)__bfloat16_as_ushort(h1) << 16) | __bfloat16_as_ushort(h0);
        uint32_t ph1 = ((uint32_t)__bfloat16_as_ushort(h3) << 16) | __bfloat16_as_ushort(h2);
        uint32_t pl0 = ((uint32_t)__bfloat16_as_ushort(l1) << 16) | __bfloat16_as_ushort(l0);
        uint32_t pl1 = ((uint32_t)__bfloat16_as_ushort(l3) << 16) | __bfloat16_as_ushort(l2);
        uint32_t o0 = (uint32_t)(row * 128 + (4 * i) * 2);
        uint32_t o1 = (uint32_t)(row * 128 + (4 * i + 2) * 2);
        o0 = o0 ^ ((o0 >> 3) & 0x70);
        o1 = o1 ^ ((o1 >> 3) & 0x70);
        *(uint32_t*)(bh + o0) = ph0;  *(uint32_t*)(bh + o1) = ph1;
        *(uint32_t*)(bl + o0) = pl0;  *(uint32_t*)(bl + o1) = pl1;
    }
    g_c2[k] = __fadd_rn(__fadd_rn(s0, s1), __fadd_rn(s2, s3));
}

// Exact fp32 distance, replicating the verified 0-flip summation structure.
static __device__ __forceinline__ float exact_dist(const float* x, const float* __restrict__ e,
                                                   float sx) {
    const float4* e4 = (const float4*)e;
    float cc0=0,cc1=0,cc2=0,cc3=0,cc4=0,cc5=0,cc6=0,cc7=0;
    float s0=0,s1=0,s2=0,s3=0;
    #pragma unroll
    for (int i = 0; i < 16; i++) {
        float4 v = e4[i];
        s0 = __fmaf_rn(v.x, v.x, s0);
        s1 = __fmaf_rn(v.y, v.y, s1);
        s2 = __fmaf_rn(v.z, v.z, s2);
        s3 = __fmaf_rn(v.w, v.w, s3);
        float x0 = x[4*i], x1 = x[4*i+1], x2 = x[4*i+2], x3 = x[4*i+3];
        if ((i & 1) == 0) {
            cc0 = __fmaf_rn(x0, v.x, cc0); cc1 = __fmaf_rn(x1, v.y, cc1);
            cc2 = __fmaf_rn(x2, v.z, cc2); cc3 = __fmaf_rn(x3, v.w, cc3);
        } else {
            cc4 = __fmaf_rn(x0, v.x, cc4); cc5 = __fmaf_rn(x1, v.y, cc5);
            cc6 = __fmaf_rn(x2, v.z, cc6); cc7 = __fmaf_rn(x3, v.w, cc7);
        }
    }
    float c2 = __fadd_rn(__fadd_rn(s0, s1), __fadd_rn(s2, s3));
    float lo = __fadd_rn(__fadd_rn(cc0, cc2), __fadd_rn(cc4, cc6));
    float hi = __fadd_rn(__fadd_rn(cc1, cc3), __fadd_rn(cc5, cc7));
    float dot = __fadd_rn(lo, hi);
    return __fsub_rn(__fadd_rn(sx, c2), __fmul_rn(2.0f, dot));
}

__global__ __launch_bounds__(BLKPIX, 2) void vq_main(const float* __restrict__ in,
                                                     const float* __restrict__ emb,
                                                     float* __restrict__ out,
                                                     int out_size) {
    extern __shared__ char sm[];
    const uint32_t sb = s2u(sm);
    const int tid  = threadIdx.x;
    const int lane = tid & 31;
    const int q    = lane >> 2;        // 0..7
    const int qp   = lane & 3;         // 0..3
    const int wrow = (tid >> 5) * 32;  // warp's 32-pixel stripe

    // ---- prologue: stage c2, load+split x into A hi/lo, prefetch B tile 0 ----
    {
        float* sc2 = (float*)(sm + SM_C2);
        #pragma unroll
        for (int i = 0; i < 4; i++) sc2[tid + i * BLKPIX] = g_c2[tid + i * BLKPIX];
    }
    const int p0 = blockIdx.x * BLKPIX + tid;
    const int b0 = p0 >> 12, h0i = (p0 >> 6) & 63, w0 = p0 & 63;
    const float* xin = in + ((b0 * 64) * 64 + h0i) * 64 + w0;
    #pragma unroll
    for (int c = 0; c < 64; c += 2) {
        float f0 = xin[c * HWv], f1 = xin[(c + 1) * HWv];
        __nv_bfloat16 hh0 = __float2bfloat16(f0), hh1 = __float2bfloat16(f1);
        __nv_bfloat16 ll0 = __float2bfloat16(__fsub_rn(f0, __bfloat162float(hh0)));
        __nv_bfloat16 ll1 = __float2bfloat16(__fsub_rn(f1, __bfloat162float(hh1)));
        uint32_t ph = ((uint32_t)__bfloat16_as_ushort(hh1) << 16) | __bfloat16_as_ushort(hh0);
        uint32_t pl = ((uint32_t)__bfloat16_as_ushort(ll1) << 16) | __bfloat16_as_ushort(ll0);
        uint32_t off = (uint32_t)(tid * 128 + c * 2);
        off = off ^ ((off >> 3) & 0x70);
        *(uint32_t*)(sm + SM_AHI + off) = ph;
        *(uint32_t*)(sm + SM_ALO + off) = pl;
    }
    #pragma unroll
    for (int j = 0; j < 4; j++) {
        cp16(sb + SM_BH + tid * 16 + j * 4096, g_bh[0] + tid * 16 + j * 4096);
        cp16(sb + SM_BL + tid * 16 + j * 4096, g_bl[0] + tid * 16 + j * 4096);
    }
    asm volatile("cp.async.commit_group;" ::: "memory");

    // top-2 as unsigned-max of raw float bits (negative dists: bits increase with |dist|),
    // complemented 10-bit index in low bits => max picks smallest code on ties.
    unsigned t1[4] = {0, 0, 0, 0};
    unsigned t2[4] = {0, 0, 0, 0};

    for (int t = 0; t < NTILES; t++) {
        asm volatile("cp.async.wait_group 0;" ::: "memory");
        __syncthreads();

        #pragma unroll
        for (int half = 0; half < 2; half++) {
            float acc[16][4];
            #pragma unroll
            for (int f = 0; f < 16; f++) {
                acc[f][0] = 0.f; acc[f][1] = 0.f; acc[f][2] = 0.f; acc[f][3] = 0.f;
            }
            const int rowB = half * 64 + (lane & 7) + ((lane >> 4) << 3);
            #pragma unroll
            for (int ks = 0; ks < 4; ks++) {
                const int akb = ks * 32 + (lane >> 4) * 16;
                const int bkb = ks * 32 + ((lane >> 3) & 1) * 16;
                uint32_t Ax[8], Bx[16];
                LDSM4(Ax,     swz(sb + SM_AHI, wrow + (lane & 15), akb));
                LDSM4(Ax + 4, swz(sb + SM_AHI, wrow + 16 + (lane & 15), akb));
                #pragma unroll
                for (int j = 0; j < 4; j++)
                    LDSM4(Bx + 4 * j, swz(sb + SM_BH, rowB + j * 16, bkb));
                #pragma unroll
                for (int cf = 0; cf < 8; cf++) {           // hh
                    MMA(acc[cf*2+0], Ax,     Bx + cf*2);
                    MMA(acc[cf*2+1], Ax + 4, Bx + cf*2);
                }
                uint32_t Ay[8];
                LDSM4(Ay,     swz(sb + SM_ALO, wrow + (lane & 15), akb));
                LDSM4(Ay + 4, swz(sb + SM_ALO, wrow + 16 + (lane & 15), akb));
                #pragma unroll
                for (int cf = 0; cf < 8; cf++) {           // lh
                    MMA(acc[cf*2+0], Ay,     Bx + cf*2);
                    MMA(acc[cf*2+1], Ay + 4, Bx + cf*2);
                }
                #pragma unroll
                for (int j = 0; j < 4; j++)                // Bl overwrites Bh regs
                    LDSM4(Bx + 4 * j, swz(sb + SM_BL, rowB + j * 16, bkb));
                #pragma unroll
                for (int cf = 0; cf < 8; cf++) {           // hl
                    MMA(acc[cf*2+0], Ax,     Bx + cf*2);
                    MMA(acc[cf*2+1], Ax + 4, Bx + cf*2);
                }
            }
            // reduce: dist = c2 - 2*dot (per-pixel sx dropped), unsigned-max top-2
            const float* c2b = (const float*)(sm + SM_C2) + t * 128 + half * 64 + qp * 2;
            const unsigned ccb = 1023u - (unsigned)(t * 128 + half * 64 + qp * 2);
            #pragma unroll
            for (int cf = 0; cf < 8; cf++) {
                float c0 = c2b[cf * 8];
                float c1 = c2b[cf * 8 + 1];
                unsigned cc0 = ccb - (unsigned)(cf * 8);
                unsigned cc1 = cc0 - 1u;
                #pragma unroll
                for (int m = 0; m < 2; m++) {
                    #pragma unroll
                    for (int i = 0; i < 4; i++) {
                        float dist = __fmaf_rn(-2.0f, acc[cf*2+m][i], (i & 1) ? c1 : c0);
                        unsigned km = (__float_as_uint(dist) & 0xFFFFFC00u)
                                      | ((i & 1) ? cc1 : cc0);
                        const int s = m * 2 + (i >> 1);
                        unsigned mn = uminu(t1[s], km);
                        t1[s] = umaxu(t1[s], km);
                        t2[s] = umaxu(t2[s], mn);
                    }
                }
            }
        }

        __syncthreads();
        if (t < NTILES - 1) {
            #pragma unroll
            for (int j = 0; j < 4; j++) {
                cp16(sb + SM_BH + tid * 16 + j * 4096, g_bh[t + 1] + tid * 16 + j * 4096);
                cp16(sb + SM_BL + tid * 16 + j * 4096, g_bl[t + 1] + tid * 16 + j * 4096);
            }
            asm volatile("cp.async.commit_group;" ::: "memory");
        }
    }

    // merge top-2 across the quad (max-merge)
    #pragma unroll
    for (int s = 0; s < 4; s++) {
        #pragma unroll
        for (int mk = 1; mk <= 2; mk <<= 1) {
            unsigned r1 = __shfl_xor_sync(0xffffffffu, t1[s], mk);
            unsigned r2 = __shfl_xor_sync(0xffffffffu, t2[s], mk);
            unsigned lo = uminu(t1[s], r1);
            t1[s] = umaxu(t1[s], r1);
            t2[s] = umaxu(lo, umaxu(t2[s], r2));
        }
    }
    unsigned f1 = t1[0], f2 = t2[0];
    if (qp == 1) { f1 = t1[1]; f2 = t2[1]; }
    if (qp == 2) { f1 = t1[2]; f2 = t2[2]; }
    if (qp == 3) { f1 = t1[3]; f2 = t2[3]; }

    const int p_local = wrow + q + qp * 8;
    const int p = blockIdx.x * BLKPIX + p_local;
    const int b = p >> 12, h = (p >> 6) & 63, w = p & 63;

    // ---- exact fp32 rescore of both candidates (x reloaded from global) ----
    const float* xg = in + ((b * 64) * 64 + h) * 64 + w;
    float x_[64];
    #pragma unroll
    for (int c = 0; c < 64; c++) x_[c] = xg[c * HWv];
    float s0 = 0.f, s1 = 0.f, s2 = 0.f, s3 = 0.f;
    #pragma unroll
    for (int i = 0; i < 32; i++) {
        float f0v = x_[2*i], f1v = x_[2*i + 1];
        if (i & 1) { s1 = __fmaf_rn(f0v, f0v, s1); s3 = __fmaf_rn(f1v, f1v, s3); }
        else       { s0 = __fmaf_rn(f0v, f0v, s0); s2 = __fmaf_rn(f1v, f1v, s2); }
    }
    const float sx = __fadd_rn(__fadd_rn(s0, s1), __fadd_rn(s2, s3));
    const int k1 = 1023 - (int)(f1 & 1023u);
    const int k2 = 1023 - (int)(f2 & 1023u);
    const float d1 = exact_dist(x_, emb + k1 * 64, sx);
    const float d2 = exact_dist(x_, emb + k2 * 64, sx);
    const int kwin = ((d2 < d1) || (d2 == d1 && k2 < k1)) ? k2 : k1;

    // ---- write quantized output (BCHW) + loss partial ----
    const float4* eb = (const float4*)(emb + kwin * 64);
    float* op = out + ((b * 64) * 64 + h) * 64 + w;
    float ls = 0.f;
    #pragma unroll
    for (int i = 0; i < 16; i++) {
        float4 qv = eb[i];
        op[(4*i + 0) * HWv] = qv.x;
        op[(4*i + 1) * HWv] = qv.y;
        op[(4*i + 2) * HWv] = qv.z;
        op[(4*i + 3) * HWv] = qv.w;
        float e0 = qv.x - x_[4*i],   e1 = qv.y - x_[4*i+1];
        float e2 = qv.z - x_[4*i+2], e3 = qv.w - x_[4*i+3];
        ls += e0*e0 + e1*e1 + e2*e2 + e3*e3;
    }
    #pragma unroll
    for (int off = 16; off; off >>= 1)
        ls += __shfl_xor_sync(0xffffffffu, ls, off);
    if (lane == 0) atomicAdd(&g_loss, ls);

    // ---- last-block ticket: finalize loss, reset for next graph replay ----
    __syncthreads();
    if (tid == 0) {
        __threadfence();
        unsigned v = atomicAdd(&g_count, 1u);
        if (v == GRIDv - 1) {
            __threadfence();
            if (out_size > NUMELv)
                out[NUMELv] = 1.25f * g_loss / (float)NUMELv;
            g_loss = 0.f;
            g_count = 0u;
        }
    }
}

extern "C" void kernel_launch(void* const* d_in, const int* in_sizes, int n_in,
                              void* d_out, int out_size) {
    const float* in  = (const float*)d_in[0];
    const float* emb = (const float*)d_in[1];
    float* out = (float*)d_out;

    vq_prep<<<NTILES, NT>>>(emb);
    cudaFuncSetAttribute(vq_main, cudaFuncAttributeMaxDynamicSharedMemorySize, SM_TOTAL);
    vq_main<<<GRIDv, BLKPIX, SM_TOTAL>>>(in, emb, out, out_size);
}

// round 6
// speedup vs baseline: 4.7958x; 1.0132x over previous
#include <cuda_runtime.h>
#include <cuda_bf16.h>
#include <stdint.h>

// Problem constants
#define HWv 4096
#define NPIXv 65536
#define NUMELv 4194304
#define NT 128               // codes per tile
#define NTILES 8
#define BLKPIX 256           // pixels per block
#define GRIDv (NPIXv/BLKPIX) // 256 blocks -> exactly 1 wave at 2 CTAs/SM

// Dynamic SMEM layout (bytes)
#define SM_AHI 0            // 256 rows x 128B (x hi, SW128)
#define SM_ALO 32768        // 256 rows x 128B (x lo)
#define SM_BH  65536        // 128 rows x 128B (codes hi)
#define SM_BL  81920        // 128 rows x 128B (codes lo)
#define SM_C2  98304        // 1024 floats
#define SM_TOTAL (98304 + 4096)

// Prepacked codebook: exact byte image of the swizzled smem B tiles.
__device__ __align__(16) unsigned char g_bh[NTILES][16384];
__device__ __align__(16) unsigned char g_bl[NTILES][16384];
__device__ float    g_c2[1024];
__device__ float    g_loss;
__device__ unsigned g_count;

static __device__ __forceinline__ uint32_t s2u(const void* p) {
    uint32_t a;
    asm("{ .reg .u64 t; cvta.to.shared.u64 t, %1; cvt.u32.u64 %0, t; }" : "=r"(a) : "l"(p));
    return a;
}
static __device__ __forceinline__ uint32_t swz(uint32_t base, int row, int kb) {
    uint32_t o = (uint32_t)(row * 128 + kb);
    return base + (o ^ ((o >> 3) & 0x70));
}
static __device__ __forceinline__ unsigned umaxu(unsigned a, unsigned b) { return a > b ? a : b; }
static __device__ __forceinline__ unsigned uminu(unsigned a, unsigned b) { return a < b ? a : b; }

#define LDSM4(R, addr) \
    asm volatile("ldmatrix.sync.aligned.m8n8.x4.shared.b16 {%0,%1,%2,%3}, [%4];" \
        : "=r"((R)[0]), "=r"((R)[1]), "=r"((R)[2]), "=r"((R)[3]) : "r"(addr))
#define MMA(D, A, B) \
    asm volatile("mma.sync.aligned.m16n8k16.row.col.f32.bf16.bf16.f32 " \
        "{%0,%1,%2,%3}, {%4,%5,%6,%7}, {%8,%9}, {%0,%1,%2,%3};" \
        : "+f"((D)[0]), "+f"((D)[1]), "+f"((D)[2]), "+f"((D)[3]) \
        : "r"((A)[0]), "r"((A)[1]), "r"((A)[2]), "r"((A)[3]), "r"((B)[0]), "r"((B)[1]))

static __device__ __forceinline__ void cp16(uint32_t dst, const void* src) {
    uint64_t g;
    asm("cvta.to.global.u64 %0, %1;" : "=l"(g) : "l"(src));
    asm volatile("cp.async.cg.shared.global [%0], [%1], 16;" :: "r"(dst), "l"(g));
}

// --- Kernel 0: prepack codebook (bf16 hi/lo, SW128 tile image) + c2 ---------
__global__ __launch_bounds__(NT) void vq_prep(const float* __restrict__ emb) {
    const int t = blockIdx.x, row = threadIdx.x;
    const int k = t * NT + row;
    const float4* er = (const float4*)(emb + k * 64);
    unsigned char* bh = g_bh[t];
    unsigned char* bl = g_bl[t];
    float s0 = 0.f, s1 = 0.f, s2 = 0.f, s3 = 0.f;
    #pragma unroll
    for (int i = 0; i < 16; i++) {
        float4 v = er[i];
        s0 = __fmaf_rn(v.x, v.x, s0);
        s1 = __fmaf_rn(v.y, v.y, s1);
        s2 = __fmaf_rn(v.z, v.z, s2);
        s3 = __fmaf_rn(v.w, v.w, s3);
        __nv_bfloat16 h0 = __float2bfloat16(v.x), h1 = __float2bfloat16(v.y);
        __nv_bfloat16 h2 = __float2bfloat16(v.z), h3 = __float2bfloat16(v.w);
        __nv_bfloat16 l0 = __float2bfloat16(__fsub_rn(v.x, __bfloat162float(h0)));
        __nv_bfloat16 l1 = __float2bfloat16(__fsub_rn(v.y, __bfloat162float(h1)));
        __nv_bfloat16 l2 = __float2bfloat16(__fsub_rn(v.z, __bfloat162float(h2)));
        __nv_bfloat16 l3 = __float2bfloat16(__fsub_rn(v.w, __bfloat162float(h3)));
        uint32_t ph0 = ((uint32_t)__bfloat16_as_ushort(h1) << 16) | __bfloat16_as_ushort(h0);
        uint32_t ph1 = ((uint32_t)__bfloat16_as_ushort(h3) << 16) | __bfloat16_as_ushort(h2);
        uint32_t pl0 = ((uint32_t)__bfloat16_as_ushort(l1) << 16) | __bfloat16_as_ushort(l0);
        uint32_t pl1 = ((uint32_t)__bfloat16_as_ushort(l3) << 16) | __bfloat16_as_ushort(l2);
        uint32_t o0 = (uint32_t)(row * 128 + (4 * i) * 2);
        uint32_t o1 = (uint32_t)(row * 128 + (4 * i + 2) * 2);
        o0 = o0 ^ ((o0 >> 3) & 0x70);
        o1 = o1 ^ ((o1 >> 3) & 0x70);
        *(uint32_t*)(bh + o0) = ph0;  *(uint32_t*)(bh + o1) = ph1;
        *(uint32_t*)(bl + o0) = pl0;  *(uint32_t*)(bl + o1) = pl1;
    }
    g_c2[k] = __fadd_rn(__fadd_rn(s0, s1), __fadd_rn(s2, s3));
}

// Exact fp32 distance, replicating the verified 0-flip summation structure.
static __device__ __forceinline__ float exact_dist(const float* x, const float* __restrict__ e,
                                                   float sx) {
    const float4* e4 = (const float4*)e;
    float cc0=0,cc1=0,cc2=0,cc3=0,cc4=0,cc5=0,cc6=0,cc7=0;
    float s0=0,s1=0,s2=0,s3=0;
    #pragma unroll
    for (int i = 0; i < 16; i++) {
        float4 v = e4[i];
        s0 = __fmaf_rn(v.x, v.x, s0);
        s1 = __fmaf_rn(v.y, v.y, s1);
        s2 = __fmaf_rn(v.z, v.z, s2);
        s3 = __fmaf_rn(v.w, v.w, s3);
        float x0 = x[4*i], x1 = x[4*i+1], x2 = x[4*i+2], x3 = x[4*i+3];
        if ((i & 1) == 0) {
            cc0 = __fmaf_rn(x0, v.x, cc0); cc1 = __fmaf_rn(x1, v.y, cc1);
            cc2 = __fmaf_rn(x2, v.z, cc2); cc3 = __fmaf_rn(x3, v.w, cc3);
        } else {
            cc4 = __fmaf_rn(x0, v.x, cc4); cc5 = __fmaf_rn(x1, v.y, cc5);
            cc6 = __fmaf_rn(x2, v.z, cc6); cc7 = __fmaf_rn(x3, v.w, cc7);
        }
    }
    float c2 = __fadd_rn(__fadd_rn(s0, s1), __fadd_rn(s2, s3));
    float lo = __fadd_rn(__fadd_rn(cc0, cc2), __fadd_rn(cc4, cc6));
    float hi = __fadd_rn(__fadd_rn(cc1, cc3), __fadd_rn(cc5, cc7));
    float dot = __fadd_rn(lo, hi);
    return __fsub_rn(__fadd_rn(sx, c2), __fmul_rn(2.0f, dot));
}

__global__ __launch_bounds__(BLKPIX, 2) void vq_main(const float* __restrict__ in,
                                                     const float* __restrict__ emb,
                                                     float* __restrict__ out,
                                                     int out_size) {
    extern __shared__ char sm[];
    const uint32_t sb = s2u(sm);
    const int tid  = threadIdx.x;
    const int lane = tid & 31;
    const int q    = lane >> 2;        // 0..7
    const int qp   = lane & 3;         // 0..3
    const int wrow = (tid >> 5) * 32;  // warp's 32-pixel stripe

    // ---- prologue: stage c2, load+split x into A hi/lo, prefetch B tile 0 ----
    {
        float* sc2 = (float*)(sm + SM_C2);
        #pragma unroll
        for (int i = 0; i < 4; i++) sc2[tid + i * BLKPIX] = g_c2[tid + i * BLKPIX];
    }
    const int p0 = blockIdx.x * BLKPIX + tid;
    const int b0 = p0 >> 12, h0i = (p0 >> 6) & 63, w0 = p0 & 63;
    const float* xin = in + ((b0 * 64) * 64 + h0i) * 64 + w0;
    #pragma unroll
    for (int c = 0; c < 64; c += 2) {
        float f0 = xin[c * HWv], f1 = xin[(c + 1) * HWv];
        __nv_bfloat16 hh0 = __float2bfloat16(f0), hh1 = __float2bfloat16(f1);
        __nv_bfloat16 ll0 = __float2bfloat16(__fsub_rn(f0, __bfloat162float(hh0)));
        __nv_bfloat16 ll1 = __float2bfloat16(__fsub_rn(f1, __bfloat162float(hh1)));
        uint32_t ph = ((uint32_t)__bfloat16_as_ushort(hh1) << 16) | __bfloat16_as_ushort(hh0);
        uint32_t pl = ((uint32_t)__bfloat16_as_ushort(ll1) << 16) | __bfloat16_as_ushort(ll0);
        uint32_t off = (uint32_t)(tid * 128 + c * 2);
        off = off ^ ((off >> 3) & 0x70);
        *(uint32_t*)(sm + SM_AHI + off) = ph;
        *(uint32_t*)(sm + SM_ALO + off) = pl;
    }
    #pragma unroll
    for (int j = 0; j < 4; j++) {
        cp16(sb + SM_BH + tid * 16 + j * 4096, g_bh[0] + tid * 16 + j * 4096);
        cp16(sb + SM_BL + tid * 16 + j * 4096, g_bl[0] + tid * 16 + j * 4096);
    }
    asm volatile("cp.async.commit_group;" ::: "memory");

    // top-2 as unsigned-max of raw float bits (negative dists: bits increase with |dist|),
    // complemented 10-bit index in low bits => max picks smallest code on ties.
    unsigned t1[4] = {0, 0, 0, 0};
    unsigned t2[4] = {0, 0, 0, 0};

    for (int t = 0; t < NTILES; t++) {
        asm volatile("cp.async.wait_group 0;" ::: "memory");
        __syncthreads();

        #pragma unroll
        for (int half = 0; half < 2; half++) {
            float acc[16][4];
            #pragma unroll
            for (int f = 0; f < 16; f++) {
                acc[f][0] = 0.f; acc[f][1] = 0.f; acc[f][2] = 0.f; acc[f][3] = 0.f;
            }
            const int rowB = half * 64 + (lane & 7) + ((lane >> 4) << 3);
            #pragma unroll
            for (int ks = 0; ks < 4; ks++) {
                const int akb = ks * 32 + (lane >> 4) * 16;
                const int bkb = ks * 32 + ((lane >> 3) & 1) * 16;
                uint32_t Ax[8], Bx[16];
                LDSM4(Ax,     swz(sb + SM_AHI, wrow + (lane & 15), akb));
                LDSM4(Ax + 4, swz(sb + SM_AHI, wrow + 16 + (lane & 15), akb));
                #pragma unroll
                for (int j = 0; j < 4; j++)
                    LDSM4(Bx + 4 * j, swz(sb + SM_BH, rowB + j * 16, bkb));
                #pragma unroll
                for (int cf = 0; cf < 8; cf++) {           // hh
                    MMA(acc[cf*2+0], Ax,     Bx + cf*2);
                    MMA(acc[cf*2+1], Ax + 4, Bx + cf*2);
                }
                uint32_t Ay[8];
                LDSM4(Ay,     swz(sb + SM_ALO, wrow + (lane & 15), akb));
                LDSM4(Ay + 4, swz(sb + SM_ALO, wrow + 16 + (lane & 15), akb));
                #pragma unroll
                for (int cf = 0; cf < 8; cf++) {           // lh
                    MMA(acc[cf*2+0], Ay,     Bx + cf*2);
                    MMA(acc[cf*2+1], Ay + 4, Bx + cf*2);
                }
                #pragma unroll
                for (int j = 0; j < 4; j++)                // Bl overwrites Bh regs
                    LDSM4(Bx + 4 * j, swz(sb + SM_BL, rowB + j * 16, bkb));
                #pragma unroll
                for (int cf = 0; cf < 8; cf++) {           // hl
                    MMA(acc[cf*2+0], Ax,     Bx + cf*2);
                    MMA(acc[cf*2+1], Ax + 4, Bx + cf*2);
                }
            }
            // reduce: dist = c2 - 2*dot (per-pixel sx dropped), unsigned-max top-2
            const float* c2b = (const float*)(sm + SM_C2) + t * 128 + half * 64 + qp * 2;
            const unsigned ccb = 1023u - (unsigned)(t * 128 + half * 64 + qp * 2);
            #pragma unroll
            for (int cf = 0; cf < 8; cf++) {
                float c0 = c2b[cf * 8];
                float c1 = c2b[cf * 8 + 1];
                unsigned cc0 = ccb - (unsigned)(cf * 8);
                unsigned cc1 = cc0 - 1u;
                #pragma unroll
                for (int m = 0; m < 2; m++) {
                    #pragma unroll
                    for (int i = 0; i < 4; i++) {
                        float dist = __fmaf_rn(-2.0f, acc[cf*2+m][i], (i & 1) ? c1 : c0);
                        unsigned km = (__float_as_uint(dist) & 0xFFFFFC00u)
                                      | ((i & 1) ? cc1 : cc0);
                        const int s = m * 2 + (i >> 1);
                        unsigned mn = uminu(t1[s], km);
                        t1[s] = umaxu(t1[s], km);
                        t2[s] = umaxu(t2[s], mn);
                    }
                }
            }
        }

        __syncthreads();
        if (t < NTILES - 1) {
            #pragma unroll
            for (int j = 0; j < 4; j++) {
                cp16(sb + SM_BH + tid * 16 + j * 4096, g_bh[t + 1] + tid * 16 + j * 4096);
                cp16(sb + SM_BL + tid * 16 + j * 4096, g_bl[t + 1] + tid * 16 + j * 4096);
            }
            asm volatile("cp.async.commit_group;" ::: "memory");
        }
    }

    // merge top-2 across the quad (max-merge)
    #pragma unroll
    for (int s = 0; s < 4; s++) {
        #pragma unroll
        for (int mk = 1; mk <= 2; mk <<= 1) {
            unsigned r1 = __shfl_xor_sync(0xffffffffu, t1[s], mk);
            unsigned r2 = __shfl_xor_sync(0xffffffffu, t2[s], mk);
            unsigned lo = uminu(t1[s], r1);
            t1[s] = umaxu(t1[s], r1);
            t2[s] = umaxu(lo, umaxu(t2[s], r2));
        }
    }
    unsigned f1 = t1[0], f2 = t2[0];
    if (qp == 1) { f1 = t1[1]; f2 = t2[1]; }
    if (qp == 2) { f1 = t1[2]; f2 = t2[2]; }
    if (qp == 3) { f1 = t1[3]; f2 = t2[3]; }

    const int p_local = wrow + q + qp * 8;
    const int p = blockIdx.x * BLKPIX + p_local;
    const int b = p >> 12, h = (p >> 6) & 63, w = p & 63;

    // ---- exact fp32 rescore of both candidates (x reloaded from global) ----
    const float* xg = in + ((b * 64) * 64 + h) * 64 + w;
    float x_[64];
    #pragma unroll
    for (int c = 0; c < 64; c++) x_[c] = xg[c * HWv];
    float s0 = 0.f, s1 = 0.f, s2 = 0.f, s3 = 0.f;
    #pragma unroll
    for (int i = 0; i < 32; i++) {
        float f0v = x_[2*i], f1v = x_[2*i + 1];
        if (i & 1) { s1 = __fmaf_rn(f0v, f0v, s1); s3 = __fmaf_rn(f1v, f1v, s3); }
        else       { s0 = __fmaf_rn(f0v, f0v, s0); s2 = __fmaf_rn(f1v, f1v, s2); }
    }
    const float sx = __fadd_rn(__fadd_rn(s0, s1), __fadd_rn(s2, s3));
    const int k1 = 1023 - (int)(f1 & 1023u);
    const int k2 = 1023 - (int)(f2 & 1023u);
    const float d1 = exact_dist(x_, emb + k1 * 64, sx);
    const float d2 = exact_dist(x_, emb + k2 * 64, sx);
    const int kwin = ((d2 < d1) || (d2 == d1 && k2 < k1)) ? k2 : k1;

    // ---- write quantized output (BCHW) + loss partial ----
    const float4* eb = (const float4*)(emb + kwin * 64);
    float* op = out + ((b * 64) * 64 + h) * 64 + w;
    float ls = 0.f;
    #pragma unroll
    for (int i = 0; i < 16; i++) {
        float4 qv = eb[i];
        op[(4*i + 0) * HWv] = qv.x;
        op[(4*i + 1) * HWv] = qv.y;
        op[(4*i + 2) * HWv] = qv.z;
        op[(4*i + 3) * HWv] = qv.w;
        float e0 = qv.x - x_[4*i],   e1 = qv.y - x_[4*i+1];
        float e2 = qv.z - x_[4*i+2], e3 = qv.w - x_[4*i+3];
        ls += e0*e0 + e1*e1 + e2*e2 + e3*e3;
    }
    #pragma unroll
    for (int off = 16; off; off >>= 1)
        ls += __shfl_xor_sync(0xffffffffu, ls, off);
    if (lane == 0) atomicAdd(&g_loss, ls);

    // ---- last-block ticket: finalize loss, reset for next graph replay ----
    __syncthreads();
    if (tid == 0) {
        __threadfence();
        unsigned v = atomicAdd(&g_count, 1u);
        if (v == GRIDv - 1) {
            __threadfence();
            if (out_size > NUMELv)
                out[NUMELv] = 1.25f * g_loss / (float)NUMELv;
            g_loss = 0.f;
            g_count = 0u;
        }
    }
}

extern "C" void kernel_launch(void* const* d_in, const int* in_sizes, int n_in,
                              void* d_out, int out_size) {
    const float* in  = (const float*)d_in[0];
    const float* emb = (const float*)d_in[1];
    float* out = (float*)d_out;

    vq_prep<<<NTILES, NT>>>(emb);
    cudaFuncSetAttribute(vq_main, cudaFuncAttributeMaxDynamicSharedMemorySize, SM_TOTAL);
    vq_main<<<GRIDv, BLKPIX, SM_TOTAL>>>(in, emb, out, out_size);
}